// round 10
// baseline (speedup 1.0000x reference)
#include <cuda_runtime.h>
#include <math.h>

#define BN   512     // B*N
#define FEAT 384
#define FFN  768
#define ZD   384
#define HID  192
#define NB   4
#define NN   128
#define LN_EPS 1e-5f
#define XLD  388     // padded smem row stride (floats)

typedef unsigned long long ull;

// ---------------- scratch (device globals; no allocation) ----------------
__device__ __align__(16) float g_xh[BN * ZD];   // gelu'd first half
__device__ __align__(16) float g_z[BN * ZD];    // RAW gelu second half (LN in k2)
__device__ __align__(16) float g_c0[ZD];
__device__ float g_diag[BN];
__device__ float g_off[BN];
__device__ float g_eo[BN];
__device__ float g_wd[BN];
__device__ float g_rD[BN];

__device__ __forceinline__ float gelu_exact(float x) {
    return 0.5f * x * (1.0f + erff(x * 0.70710678118654752440f));
}
// packed f32x2 helpers (sm_103a)
__device__ __forceinline__ ull dup2(float x) {
    ull r; asm("mov.b64 %0, {%1, %1};" : "=l"(r) : "f"(x)); return r;
}
__device__ __forceinline__ void fma2(ull &d, ull a, ull b) {
    asm("fma.rn.f32x2 %0, %1, %2, %0;" : "+l"(d) : "l"(a), "l"(b));
}
__device__ __forceinline__ float2 unp2(ull v) {
    float2 f; asm("mov.b64 {%0, %1}, %2;" : "=f"(f.x), "=f"(f.y) : "l"(v)); return f;
}

// ---------------- k1: h = gelu(x @ U_w + U_b), tiled 16 rows x 96 cols ----
// grid 257; threads 384: cg=t%24 (4 cols), rgrp=(t/24)&3 (4 rows), kq=t/96 (96 k)
__global__ __launch_bounds__(384, 2)
void k1_gemmU(const float* __restrict__ x,
              const float* __restrict__ U_w,
              const float* __restrict__ U_b,
              const float* __restrict__ enc_b,
              const float* __restrict__ dec_w,
              const float* __restrict__ dec_b) {
    const int t = threadIdx.x;
    if (blockIdx.x == 256) {
        __shared__ float gh[HID];
        if (t < HID) gh[t] = gelu_exact(enc_b[t]);
        __syncthreads();
        float acc = dec_b[t];
        for (int ub = 0; ub < HID; ub += 8) {
            float w[8];
#pragma unroll
            for (int i = 0; i < 8; i++) w[i] = dec_w[(ub + i) * ZD + t];
#pragma unroll
            for (int i = 0; i < 8; i++) acc += gh[ub + i] * w[i];
        }
        g_c0[t] = acc;
        return;
    }
    const int ct  = blockIdx.x & 7;
    const int rt  = blockIdx.x >> 3;
    const int r0  = rt * 16;
    const int gc0 = ct * 96;

    __shared__ float sbuf[16 * XLD];      // xs, then reused as partials

#pragma unroll
    for (int i = 0; i < 4; i++) {
        int f4 = t + i * 384;
        int r = f4 / 96, kk = (f4 % 96) * 4;
        *(float4*)&sbuf[r * XLD + kk] = *(const float4*)(x + (size_t)(r0 + r) * FEAT + kk);
    }
    __syncthreads();

    const int cg   = t % 24;
    const int rgrp = (t / 24) & 3;
    const int kq   = t / 96;
    const int cc   = cg * 4;

    ull accP[4][2] = {};
    const float* wb = U_w + (size_t)(kq * 96) * FFN + gc0 + cc;
    const float* xb = &sbuf[(rgrp * 4) * XLD + kq * 96];

    ulonglong2 wA[4], wB[4];
#pragma unroll
    for (int i = 0; i < 4; i++) wA[i] = *(const ulonglong2*)(wb + (size_t)i * FFN);
    for (int kb = 0; kb < 96; kb += 8) {
#pragma unroll
        for (int i = 0; i < 4; i++)
            wB[i] = *(const ulonglong2*)(wb + (size_t)(kb + 4 + i) * FFN);
#pragma unroll
        for (int i = 0; i < 4; i++) {
            const int k = kb + i;
#pragma unroll
            for (int r = 0; r < 4; r++) {
                ull xp = dup2(xb[r * XLD + k]);
                fma2(accP[r][0], wA[i].x, xp);
                fma2(accP[r][1], wA[i].y, xp);
            }
        }
        if (kb + 8 < 96) {
#pragma unroll
            for (int i = 0; i < 4; i++)
                wA[i] = *(const ulonglong2*)(wb + (size_t)(kb + 8 + i) * FFN);
        }
#pragma unroll
        for (int i = 0; i < 4; i++) {
            const int k = kb + 4 + i;
#pragma unroll
            for (int r = 0; r < 4; r++) {
                ull xp = dup2(xb[r * XLD + k]);
                fma2(accP[r][0], wB[i].x, xp);
                fma2(accP[r][1], wB[i].y, xp);
            }
        }
    }
    __syncthreads();   // xs reads done; reuse sbuf for partials
#pragma unroll
    for (int r = 0; r < 4; r++) {
        float2 p0 = unp2(accP[r][0]), p1 = unp2(accP[r][1]);
        *(float4*)&sbuf[kq * 1536 + (rgrp * 4 + r) * 96 + cc] =
            make_float4(p0.x, p0.y, p1.x, p1.y);
    }
    __syncthreads();

#pragma unroll
    for (int i = 0; i < 4; i++) {
        int idx = t + i * 384;
        int r = idx / 96, c = idx % 96;
        float v = sbuf[r * 96 + c] + sbuf[1536 + r * 96 + c]
                + sbuf[3072 + r * 96 + c] + sbuf[4608 + r * 96 + c] + U_b[gc0 + c];
        v = gelu_exact(v);
        if (ct < 4) g_xh[(size_t)(r0 + r) * ZD + gc0 + c] = v;
        else        g_z[(size_t)(r0 + r) * ZD + (gc0 - 384) + c] = v;
    }
}

// ---------------- k2: LN + AE diag + dots, 4-row tiles --------------------
__global__ __launch_bounds__(384, 1)
void k2_ae(const float* __restrict__ enc_w,
           const float* __restrict__ enc_b,
           const float* __restrict__ dec_w,
           const float* __restrict__ dec_b,
           const float* __restrict__ ln_w,
           const float* __restrict__ ln_b) {
    const int r0 = blockIdx.x * 4;
    const int t  = threadIdx.x;
    __shared__ float zs[4 * XLD];
    __shared__ float par[6144];
    __shared__ float hs[4][HID];
    __shared__ float rs1[4][12], rs2[4][12], mu_s[4], rsd_s[4];
    __shared__ float redd[4][12], redo[4][12];

    {
        int r = t / 96, kk = (t % 96) * 4;
        *(float4*)&zs[r * XLD + kk] = *(const float4*)(g_z + (size_t)(r0 + r) * ZD + kk);
    }
    __syncthreads();

    // ---- LayerNorm ----
    const int wI = t >> 5, l = t & 31;
    float v[4];
#pragma unroll
    for (int r = 0; r < 4; r++) {
        v[r] = zs[r * XLD + t];
        float s = v[r], q = v[r] * v[r];
#pragma unroll
        for (int o = 16; o > 0; o >>= 1) {
            s += __shfl_down_sync(0xffffffffu, s, o);
            q += __shfl_down_sync(0xffffffffu, q, o);
        }
        if (l == 0) { rs1[r][wI] = s; rs2[r][wI] = q; }
    }
    __syncthreads();
    if (t < 4) {
        float s = 0.f, q = 0.f;
#pragma unroll
        for (int i = 0; i < 12; i++) { s += rs1[t][i]; q += rs2[t][i]; }
        float mu  = s * (1.0f / ZD);
        float var = q * (1.0f / ZD) - mu * mu;
        mu_s[t]  = mu;
        rsd_s[t] = rsqrtf(var + LN_EPS);
    }
    __syncthreads();
    {
        const float lw = ln_w[t], lb = ln_b[t];
#pragma unroll
        for (int r = 0; r < 4; r++)
            zs[r * XLD + t] = (v[r] - mu_s[r]) * rsd_s[r] * lw + lb;
    }
    __syncthreads();

    // ---- encoder GEMM: cg=t%48 (4 cols), kq=t/48 (8 slices of 48 k) ----
    {
        const int cg = t % 48, kq = t / 48, cc = cg * 4;
        ull accP[4][2] = {};
        const float* wb = enc_w + (size_t)(kq * 48) * HID + cc;
        for (int kb = 0; kb < 48; kb += 8) {
            ulonglong2 w[8];
#pragma unroll
            for (int i = 0; i < 8; i++)
                w[i] = *(const ulonglong2*)(wb + (size_t)(kb + i) * HID);
#pragma unroll
            for (int i = 0; i < 8; i++) {
                const int k = kq * 48 + kb + i;
#pragma unroll
                for (int r = 0; r < 4; r++) {
                    ull zp = dup2(zs[r * XLD + k]);
                    fma2(accP[r][0], w[i].x, zp);
                    fma2(accP[r][1], w[i].y, zp);
                }
            }
        }
#pragma unroll
        for (int r = 0; r < 4; r++) {
            float2 p0 = unp2(accP[r][0]), p1 = unp2(accP[r][1]);
            *(float4*)&par[kq * 768 + r * HID + cc] = make_float4(p0.x, p0.y, p1.x, p1.y);
        }
    }
    __syncthreads();
#pragma unroll
    for (int i = 0; i < 2; i++) {
        int idx = t + i * 384;
        int r = idx / HID, c = idx % HID;
        float h = enc_b[c];
#pragma unroll
        for (int q = 0; q < 8; q++) h += par[q * 768 + r * HID + c];
        hs[r][c] = gelu_exact(h);
    }
    __syncthreads();

    // ---- decoder GEMM: cg=t%96 (4 cols), kq=t/96 (4 slices of 48 u) ----
    {
        const int cg = t % 96, kq = t / 96, cc = cg * 4;
        ull accP[4][2] = {};
        const float* wb = dec_w + (size_t)(kq * 48) * ZD + cc;
        for (int ub = 0; ub < 48; ub += 8) {
            ulonglong2 w[8];
#pragma unroll
            for (int i = 0; i < 8; i++)
                w[i] = *(const ulonglong2*)(wb + (size_t)(ub + i) * ZD);
#pragma unroll
            for (int i = 0; i < 8; i++) {
                const int u = kq * 48 + ub + i;
#pragma unroll
                for (int r = 0; r < 4; r++) {
                    ull hp = dup2(hs[r][u]);
                    fma2(accP[r][0], w[i].x, hp);
                    fma2(accP[r][1], w[i].y, hp);
                }
            }
        }
#pragma unroll
        for (int r = 0; r < 4; r++) {
            float2 p0 = unp2(accP[r][0]), p1 = unp2(accP[r][1]);
            *(float4*)&par[kq * 1536 + r * ZD + cc] = make_float4(p0.x, p0.y, p1.x, p1.y);
        }
    }
    __syncthreads();

    // ---- reduce + dots ----
    const float db = dec_b[t];
    const float c0f = g_c0[t];
    float d[4], o[4];
#pragma unroll
    for (int r = 0; r < 4; r++) {
        float p = par[r * ZD + t] + par[1536 + r * ZD + t]
                + par[3072 + r * ZD + t] + par[4608 + r * ZD + t] + db;
        float zv = zs[r * XLD + t];
        d[r] = p * zv;
        o[r] = c0f * zv;
    }
#pragma unroll
    for (int r = 0; r < 4; r++) {
        float dd = d[r], oo = o[r];
#pragma unroll
        for (int s = 16; s > 0; s >>= 1) {
            dd += __shfl_down_sync(0xffffffffu, dd, s);
            oo += __shfl_down_sync(0xffffffffu, oo, s);
        }
        if (l == 0) { redd[r][wI] = dd; redo[r][wI] = oo; }
    }
    __syncthreads();
    if (t < 4) {
        float dd = 0.f, oo = 0.f;
#pragma unroll
        for (int i = 0; i < 12; i++) { dd += redd[t][i]; oo += redo[t][i]; }
        g_diag[r0 + t] = dd;
        g_off[r0 + t]  = oo;
    }
}

// ---------------- k3: softmax stats only ----------------------------------
__global__ void k3_stats() {
    const int b = blockIdx.x;
    const int t = threadIdx.x;
    __shared__ float red[5];
    float off = g_off[b * NN + t];
    float dg  = g_diag[b * NN + t];
    float m = fmaxf(off, dg);
#pragma unroll
    for (int o = 16; o > 0; o >>= 1) m = fmaxf(m, __shfl_down_sync(0xffffffffu, m, o));
    const int w = t >> 5, l = t & 31;
    if (l == 0) red[w] = m;
    __syncthreads();
    if (t == 0) red[4] = fmaxf(fmaxf(red[0], red[1]), fmaxf(red[2], red[3]));
    __syncthreads();
    m = red[4];
    float a = expf(off - m), c = expf(dg - m);
    float e1 = a;
#pragma unroll
    for (int o = 16; o > 0; o >>= 1) e1 += __shfl_down_sync(0xffffffffu, e1, o);
    if (l == 0) red[w] = e1;
    __syncthreads();
    if (t == 0) red[4] = red[0] + red[1] + red[2] + red[3];
    __syncthreads();
    const float S = red[4];
    g_eo[b * NN + t] = a;
    g_wd[b * NN + t] = c - a;
    g_rD[b * NN + t] = 1.0f / (S - a + c);
}

// ---------------- k4: T + combine + final GEMM, tiled 8x96 ----------------
// grid 256: ct=bid&3 (96-col tile), rt=bid>>2 (8-row tile)
__global__ __launch_bounds__(384, 2)
void k4_out(const float* __restrict__ V_w,
            const float* __restrict__ V_b,
            float* __restrict__ out) {
    const int ct = blockIdx.x & 3;
    const int rt = blockIdx.x >> 2;
    const int r0 = rt * 8;
    const int c0 = ct * 96;
    const int t  = threadIdx.x;
    const int b  = r0 / NN;

    __shared__ float us[8 * XLD];
    __shared__ float par[3072];
    __shared__ float eo[NN], wd[8], rd[8];
    if (t < NN) eo[t] = g_eo[b * NN + t];
    if (t >= 368 && t < 376) { int r = t - 368; wd[r] = g_wd[r0 + r]; rd[r] = g_rD[r0 + r]; }
    __syncthreads();

    // phase 1: T[t] and us rows (thread = col t)
    float T = 0.f;
    const float* xh = g_xh + (size_t)b * NN * ZD + t;
    for (int jb = 0; jb < NN; jb += 16) {
        float xv[16];
#pragma unroll
        for (int i = 0; i < 16; i++) xv[i] = xh[(size_t)(jb + i) * ZD];
#pragma unroll
        for (int i = 0; i < 16; i++) T += eo[jb + i] * xv[i];
    }
    {
        float xr[8];
#pragma unroll
        for (int r = 0; r < 8; r++) xr[r] = g_xh[(size_t)(r0 + r) * ZD + t];
#pragma unroll
        for (int r = 0; r < 8; r++)
            us[r * XLD + t] = (T + wd[r] * xr[r]) * rd[r];
    }
    __syncthreads();

    // phase 2 GEMM: cg=t%24 (4 cols), rgrp=(t/24)&3 (2 rows), kq=t/96 (96 f)
    const int cg   = t % 24;
    const int rgrp = (t / 24) & 3;
    const int kq   = t / 96;
    const int cc   = cg * 4;
    ull accP[2][2] = {};
    const float* wb = V_w + (size_t)(kq * 96) * FEAT + c0 + cc;
    const float* ub = &us[(rgrp * 2) * XLD + kq * 96];

    ulonglong2 wA[4], wB[4];
#pragma unroll
    for (int i = 0; i < 4; i++) wA[i] = *(const ulonglong2*)(wb + (size_t)i * FEAT);
    for (int fb = 0; fb < 96; fb += 8) {
#pragma unroll
        for (int i = 0; i < 4; i++)
            wB[i] = *(const ulonglong2*)(wb + (size_t)(fb + 4 + i) * FEAT);
#pragma unroll
        for (int i = 0; i < 4; i++) {
            const int f = fb + i;
#pragma unroll
            for (int r = 0; r < 2; r++) {
                ull up = dup2(ub[r * XLD + f]);
                fma2(accP[r][0], wA[i].x, up);
                fma2(accP[r][1], wA[i].y, up);
            }
        }
        if (fb + 8 < 96) {
#pragma unroll
            for (int i = 0; i < 4; i++)
                wA[i] = *(const ulonglong2*)(wb + (size_t)(fb + 8 + i) * FEAT);
        }
#pragma unroll
        for (int i = 0; i < 4; i++) {
            const int f = fb + 4 + i;
#pragma unroll
            for (int r = 0; r < 2; r++) {
                ull up = dup2(ub[r * XLD + f]);
                fma2(accP[r][0], wB[i].x, up);
                fma2(accP[r][1], wB[i].y, up);
            }
        }
    }
#pragma unroll
    for (int r = 0; r < 2; r++) {
        float2 p0 = unp2(accP[r][0]), p1 = unp2(accP[r][1]);
        *(float4*)&par[kq * 768 + (rgrp * 2 + r) * 96 + cc] =
            make_float4(p0.x, p0.y, p1.x, p1.y);
    }
    __syncthreads();

#pragma unroll
    for (int i = 0; i < 2; i++) {
        int idx = t + i * 384;
        int r = idx / 96, c = idx % 96;
        out[(size_t)(r0 + r) * FEAT + c0 + c] =
            par[r * 96 + c] + par[768 + r * 96 + c]
          + par[1536 + r * 96 + c] + par[2304 + r * 96 + c] + V_b[c0 + c];
    }
}

// ---------------- launch ---------------------------------------------------
extern "C" void kernel_launch(void* const* d_in, const int* in_sizes, int n_in,
                              void* d_out, int out_size) {
    const float* x     = (const float*)d_in[0];
    const float* U_w   = (const float*)d_in[1];
    const float* U_b   = (const float*)d_in[2];
    const float* ln_w  = (const float*)d_in[3];
    const float* ln_b  = (const float*)d_in[4];
    const float* enc_w = (const float*)d_in[5];
    const float* enc_b = (const float*)d_in[6];
    const float* dec_w = (const float*)d_in[7];
    const float* dec_b = (const float*)d_in[8];
    const float* V_w   = (const float*)d_in[9];
    const float* V_b   = (const float*)d_in[10];
    float* out = (float*)d_out;

    k1_gemmU<<<257, 384>>>(x, U_w, U_b, enc_b, dec_w, dec_b);
    k2_ae<<<128, 384>>>(enc_w, enc_b, dec_w, dec_b, ln_w, ln_b);
    k3_stats<<<NB, NN>>>();
    k4_out<<<256, 384>>>(V_w, V_b, out);
}